// round 2
// baseline (speedup 1.0000x reference)
#include <cuda_runtime.h>
#include <cuda_bf16.h>

// Conv2D 15x15 valid cross-correlation, 4096x4096 fp32 -> 4082x4082 fp32.
// Packed-fp32 (fma.rn.f32x2) direct convolution: each thread computes a
// 2(x) x 16(y) output tile, accumulators held as 16 packed f32x2 registers.
//
// Per kx:
//   even kx: column pair (c,c+1) is 8B-aligned in smem -> LDS.64 into a 64b reg
//   odd  kx: pair (c+1,c+2) built from hi(prev pair) + 1 fresh scalar (mov.b64)
//   weights pre-broadcast to {w,w} 64-bit pairs in smem (LDS.64 broadcast).
// 15(ky) x 16(ty) packed FMAs per kx, all operands in registers.

#define H_IN   4096
#define W_IN   4096
#define KH     15
#define KW     15
#define OH     (H_IN - KH + 1)   // 4082
#define OW     (W_IN - KW + 1)   // 4082

#define NT     128               // threads per block
#define BXO    (NT * 2)          // 256 output columns per block
#define TY     16                // output rows per thread
#define TROWS  (TY + KH - 1)     // 30 smem rows
#define TCOLS  (BXO + KW - 1)    // 270 valid smem cols
#define TPITCH 272               // even pitch -> 8B-aligned even columns

typedef unsigned long long u64;

__device__ __forceinline__ u64 pack2(float lo, float hi) {
    u64 r; asm("mov.b64 %0, {%1, %2};" : "=l"(r) : "f"(lo), "f"(hi)); return r;
}
__device__ __forceinline__ u64 fma2(u64 a, u64 b, u64 c) {
    u64 d; asm("fma.rn.f32x2 %0, %1, %2, %3;" : "=l"(d) : "l"(a), "l"(b), "l"(c)); return d;
}
__device__ __forceinline__ u64 add2(u64 a, u64 b) {
    u64 d; asm("add.rn.f32x2 %0, %1, %2;" : "=l"(d) : "l"(a), "l"(b)); return d;
}
// new pair = (hi(old), s)
__device__ __forceinline__ u64 shift_in(u64 old, float s) {
    u64 r;
    asm("{\n\t"
        ".reg .f32 lo, hi;\n\t"
        "mov.b64 {lo, hi}, %1;\n\t"
        "mov.b64 %0, {hi, %2};\n\t"
        "}" : "=l"(r) : "l"(old), "f"(s));
    return r;
}

__global__ __launch_bounds__(NT)
void conv15x2_kernel(const float* __restrict__ X,
                     const float* __restrict__ Wt,
                     const float* __restrict__ bias,
                     float* __restrict__ out)
{
    __shared__ __align__(16) float tile[TROWS * TPITCH];
    __shared__ u64 w2[KH * KW];

    const int tid = threadIdx.x;
    const int gx0 = blockIdx.x * BXO;
    const int gy0 = blockIdx.y * TY;

    // Pre-broadcast weights to {w,w} pairs.
    for (int i = tid; i < KH * KW; i += NT) {
        float w = Wt[i];
        w2[i] = pack2(w, w);
    }

    // Cooperative tile fill (clamped; clamped values feed only never-stored
    // accumulator lanes -> any in-bounds value is safe).
    for (int i = tid; i < TROWS * TCOLS; i += NT) {
        int r = i / TCOLS;
        int c = i - r * TCOLS;
        int gy = gy0 + r; if (gy > H_IN - 1) gy = H_IN - 1;
        int gx = gx0 + c; if (gx > W_IN - 1) gx = W_IN - 1;
        tile[r * TPITCH + c] = X[(size_t)gy * W_IN + gx];
    }
    __syncthreads();

    const int x0 = 2 * tid;           // thread's pair base column in tile
    u64 acc[TY];
    #pragma unroll
    for (int t = 0; t < TY; t++) acc[t] = 0ull;

    u64 seg[TROWS];

    // kx pairs (m, m+1) for m = 0,2,...,12 ; kx=14 handled in the tail.
    #pragma unroll 1
    for (int m = 0; m < KW - 1; m += 2) {
        // even kx = m: aligned 8B column-pair loads
        #pragma unroll
        for (int i = 0; i < TROWS; i++)
            seg[i] = *(const u64*)&tile[i * TPITCH + x0 + m];
        #pragma unroll
        for (int ky = 0; ky < KH; ky++) {
            u64 w = w2[ky * KW + m];
            #pragma unroll
            for (int ty = 0; ty < TY; ty++)
                acc[ty] = fma2(seg[ty + ky], w, acc[ty]);
        }
        // odd kx = m+1: shift pairs left by one column
        #pragma unroll
        for (int i = 0; i < TROWS; i++)
            seg[i] = shift_in(seg[i], tile[i * TPITCH + x0 + m + 2]);
        #pragma unroll
        for (int ky = 0; ky < KH; ky++) {
            u64 w = w2[ky * KW + m + 1];
            #pragma unroll
            for (int ty = 0; ty < TY; ty++)
                acc[ty] = fma2(seg[ty + ky], w, acc[ty]);
        }
    }
    { // kx = 14 (even)
        #pragma unroll
        for (int i = 0; i < TROWS; i++)
            seg[i] = *(const u64*)&tile[i * TPITCH + x0 + (KW - 1)];
        #pragma unroll
        for (int ky = 0; ky < KH; ky++) {
            u64 w = w2[ky * KW + (KW - 1)];
            #pragma unroll
            for (int ty = 0; ty < TY; ty++)
                acc[ty] = fma2(seg[ty + ky], w, acc[ty]);
        }
    }

    // Epilogue: add bias, store packed pairs (8B-aligned: OW even, ox even).
    const float b = bias[0];
    const u64 b2 = pack2(b, b);
    const int ox = gx0 + x0;
    if (ox < OW) {                     // ox even, OW even -> full pair fits
        #pragma unroll
        for (int ty = 0; ty < TY; ty++) {
            int oy = gy0 + ty;
            if (oy < OH)
                *(u64*)&out[(size_t)oy * OW + ox] = add2(acc[ty], b2);
        }
    }
}

extern "C" void kernel_launch(void* const* d_in, const int* in_sizes, int n_in,
                              void* d_out, int out_size)
{
    const float* X    = (const float*)d_in[0];  // [4096,4096]
    const float* Wt   = (const float*)d_in[1];  // [15,15]
    const float* bias = (const float*)d_in[2];  // [1]
    float* out        = (float*)d_out;          // [4082,4082]

    dim3 grid((OW + BXO - 1) / BXO,   // 16
              (OH + TY - 1) / TY);    // 256
    conv15x2_kernel<<<grid, NT>>>(X, Wt, bias, out);
}

// round 3
// speedup vs baseline: 1.2168x; 1.2168x over previous
#include <cuda_runtime.h>
#include <cuda_bf16.h>

// Conv2D 15x15 valid cross-correlation, 4096x4096 fp32 -> 4082x4082 fp32.
// Diagonal-streamed packed-fp32 (fma.rn.f32x2) direct convolution.
//
// Each thread: 2(x) x 16(y) outputs as 16 packed f32x2 accumulators.
// For each kx (15 columns), stream input rows i = 0..29; row i feeds exactly
// the taps ky with ty = i - ky, so each loaded pair is consumed immediately
// and dies -> no seg[] register array. Live regs: 16 acc pairs + 15 weight
// pairs + 1 value => ~80 regs => 6 CTAs/SM.
//
// even kx: aligned LDS.64 pair; odd kx: two scalar LDS into a reg pair.

#define H_IN   4096
#define W_IN   4096
#define KH     15
#define KW     15
#define OH     (H_IN - KH + 1)   // 4082
#define OW     (W_IN - KW + 1)   // 4082

#define NT     128               // threads per block
#define BXO    (NT * 2)          // 256 output columns per block
#define TY     16                // output rows per thread
#define TROWS  (TY + KH - 1)     // 30
#define TCOLS  (BXO + KW - 1)    // 270
#define TPITCH 272               // even pitch, 16B-aligned rows

typedef unsigned long long u64;

__device__ __forceinline__ u64 pack2(float lo, float hi) {
    u64 r; asm("mov.b64 %0, {%1, %2};" : "=l"(r) : "f"(lo), "f"(hi)); return r;
}
__device__ __forceinline__ u64 fma2(u64 a, u64 b, u64 c) {
    u64 d; asm("fma.rn.f32x2 %0, %1, %2, %3;" : "=l"(d) : "l"(a), "l"(b), "l"(c)); return d;
}
__device__ __forceinline__ u64 add2(u64 a, u64 b) {
    u64 d; asm("add.rn.f32x2 %0, %1, %2;" : "=l"(d) : "l"(a), "l"(b)); return d;
}

// Process one kernel column kx. pc points at tile[x0 + kx] (8B-aligned when
// !ODD). wp points at w2[kx] (stride KW between ky taps).
template<bool ODD>
__device__ __forceinline__ void conv_kx(const float* __restrict__ pc,
                                        const u64* __restrict__ wp,
                                        u64 (&acc)[TY])
{
    u64 wk[KH];
    #pragma unroll
    for (int ky = 0; ky < KH; ky++) wk[ky] = wp[ky * KW];

    #pragma unroll
    for (int i = 0; i < TROWS; i++) {
        u64 v;
        if (ODD) v = pack2(pc[i * TPITCH], pc[i * TPITCH + 1]);
        else     v = *(const u64*)(pc + i * TPITCH);
        const int kylo = (i - (TY - 1) > 0) ? i - (TY - 1) : 0;
        const int kyhi = (i < KH - 1) ? i : KH - 1;
        #pragma unroll
        for (int ky = 0; ky < KH; ky++)
            if (ky >= kylo && ky <= kyhi)
                acc[i - ky] = fma2(v, wk[ky], acc[i - ky]);
    }
}

__global__ __launch_bounds__(NT, 6)
void conv15d_kernel(const float* __restrict__ X,
                    const float* __restrict__ Wt,
                    const float* __restrict__ bias,
                    float* __restrict__ out)
{
    __shared__ __align__(16) float tile[TROWS * TPITCH];
    __shared__ u64 w2[KH * KW];

    const int tid = threadIdx.x;
    const int gx0 = blockIdx.x * BXO;
    const int gy0 = blockIdx.y * TY;

    // Weights as {w,w} pairs.
    for (int i = tid; i < KH * KW; i += NT) {
        float w = Wt[i];
        w2[i] = pack2(w, w);
    }

    // Tile fill. Fast float4 path for fully-interior blocks (covers cols
    // gx0..gx0+271, rows gy0..gy0+29); scalar clamped path otherwise.
    if (gx0 + TPITCH <= W_IN && gy0 + TROWS <= H_IN) {
        const int NV = TPITCH / 4;  // 68 float4 per row
        #pragma unroll 4
        for (int i = tid; i < TROWS * NV; i += NT) {
            int r = i / NV;
            int c4 = i - r * NV;
            float4 v = *(const float4*)&X[(size_t)(gy0 + r) * W_IN + gx0 + 4 * c4];
            *(float4*)&tile[r * TPITCH + 4 * c4] = v;
        }
    } else {
        for (int i = tid; i < TROWS * TCOLS; i += NT) {
            int r = i / TCOLS;
            int c = i - r * TCOLS;
            int gy = gy0 + r; if (gy > H_IN - 1) gy = H_IN - 1;
            int gx = gx0 + c; if (gx > W_IN - 1) gx = W_IN - 1;
            tile[r * TPITCH + c] = X[(size_t)gy * W_IN + gx];
        }
    }
    __syncthreads();

    const int x0 = 2 * tid;
    const float* pcol = tile + x0;

    u64 acc[TY];
    #pragma unroll
    for (int t = 0; t < TY; t++) acc[t] = 0ull;

    #pragma unroll 1
    for (int m = 0; m < KW - 1; m += 2) {
        conv_kx<false>(pcol + m,     w2 + m,     acc);
        conv_kx<true >(pcol + m + 1, w2 + m + 1, acc);
    }
    conv_kx<false>(pcol + (KW - 1), w2 + (KW - 1), acc);

    // Epilogue: bias + packed stores (ox even, OW even -> no straddle).
    const float b = bias[0];
    const u64 b2 = pack2(b, b);
    const int ox = gx0 + x0;
    if (ox + 1 < OW) {
        #pragma unroll
        for (int ty = 0; ty < TY; ty++) {
            int oy = gy0 + ty;
            if (oy < OH)
                *(u64*)&out[(size_t)oy * OW + ox] = add2(acc[ty], b2);
        }
    }
}

extern "C" void kernel_launch(void* const* d_in, const int* in_sizes, int n_in,
                              void* d_out, int out_size)
{
    const float* X    = (const float*)d_in[0];  // [4096,4096]
    const float* Wt   = (const float*)d_in[1];  // [15,15]
    const float* bias = (const float*)d_in[2];  // [1]
    float* out        = (float*)d_out;          // [4082,4082]

    dim3 grid((OW + BXO - 1) / BXO,   // 16
              (OH + TY - 1) / TY);    // 256
    conv15d_kernel<<<grid, NT>>>(X, Wt, bias, out);
}

// round 5
// speedup vs baseline: 1.2649x; 1.0395x over previous
#include <cuda_runtime.h>
#include <cuda_bf16.h>

// Conv2D 15x15 valid cross-correlation, 4096x4096 fp32 -> 4082x4082 fp32.
// Packed-fp32 (fma.rn.f32x2), parity-fused direct convolution.
//
// Each thread owns output x-pair (x0, x0+1), TY=16 rows.
// For kx-pair (m, m+1): ONE aligned LDS.64 at column x0+m feeds BOTH taps:
//   accA (lanes = out x0,   x0+1) += v * {w[ky][m],   w[ky][m]}
//   accB (lanes = out x0-1, x0  ) += v * {w[ky][m+1], w[ky][m+1]}
// End: out(x0)   = accA.lo + accB.hi               (in-thread)
//      out(x0+1) = accA.hi + accB(t+1).lo          (smem exchange; the
//      virtual t=128 column is computed directly by warp-0 lanes).
// Weights staged in shared memory (broadcast LDS, conflict-free).

#define H_IN   4096
#define W_IN   4096
#define KH     15
#define KW     15
#define OH     (H_IN - KH + 1)   // 4082
#define OW     (W_IN - KW + 1)   // 4082

#define NT     128
#define BXO    (NT * 2)          // 256 output cols per block
#define TY     16
#define TROWS  (TY + KH - 1)     // 30
#define TCOLS  (BXO + KW - 1)    // 270
#define TPITCH 272               // even pitch, rows 16B-aligned
#define XPITCH 136               // exchange-overlay pitch (floats)

typedef unsigned long long u64;

__device__ __forceinline__ u64 pack2(float lo, float hi) {
    u64 r; asm("mov.b64 %0, {%1, %2};" : "=l"(r) : "f"(lo), "f"(hi)); return r;
}
__device__ __forceinline__ void unpack2(u64 v, float& lo, float& hi) {
    asm("mov.b64 {%0, %1}, %2;" : "=f"(lo), "=f"(hi) : "l"(v));
}
__device__ __forceinline__ u64 fma2(u64 a, u64 b, u64 c) {
    u64 d; asm("fma.rn.f32x2 %0, %1, %2, %3;" : "=l"(d) : "l"(a), "l"(b), "l"(c)); return d;
}

__global__ __launch_bounds__(NT)
void conv15f_kernel(const float* __restrict__ X,
                    const float* __restrict__ Wt,
                    const float* __restrict__ bias,
                    float* __restrict__ out)
{
    __shared__ __align__(16) float tile[TROWS * TPITCH];
    __shared__ float wsh[KH * KW];

    const int tid = threadIdx.x;
    const int gx0 = blockIdx.x * BXO;
    const int gy0 = blockIdx.y * TY;

    if (tid < KH * KW) wsh[tid] = Wt[tid];
    if (tid + NT < KH * KW) wsh[tid + NT] = Wt[tid + NT];

    // ---- tile fill (float4 fast path for interior blocks) ----
    if (gx0 + TPITCH <= W_IN && gy0 + TROWS <= H_IN) {
        const int NV = TPITCH / 4;  // 68 float4 per row
        #pragma unroll 4
        for (int i = tid; i < TROWS * NV; i += NT) {
            int r = i / NV;
            int c4 = i - r * NV;
            float4 v = *(const float4*)&X[(size_t)(gy0 + r) * W_IN + gx0 + 4 * c4];
            *(float4*)&tile[r * TPITCH + 4 * c4] = v;
        }
    } else {
        for (int i = tid; i < TROWS * TCOLS; i += NT) {
            int r = i / TCOLS;
            int c = i - r * TCOLS;
            int gy = gy0 + r; if (gy > H_IN - 1) gy = H_IN - 1;
            int gx = gx0 + c; if (gx > W_IN - 1) gx = W_IN - 1;
            tile[r * TPITCH + c] = X[(size_t)gy * W_IN + gx];
        }
    }
    const float b = bias[0];
    __syncthreads();

    const int x0 = 2 * tid;
    const float* pc = tile + x0;

    u64 accA[TY], accB[TY];
    #pragma unroll
    for (int t = 0; t < TY; t++) { accA[t] = 0ull; accB[t] = 0ull; }

    // ---- main loop: 7 kx-pairs, one load stream feeds both parities ----
    #pragma unroll 1
    for (int m = 0; m < KW - 1; m += 2) {
        const float* p = pc + m;
        // phase 1: ky 0..7, rows 0..22
        {
            u64 wA[8], wB[8];
            #pragma unroll
            for (int ky = 0; ky < 8; ky++) {
                float a  = wsh[ky * KW + m];
                float bb = wsh[ky * KW + m + 1];
                wA[ky] = pack2(a, a);
                wB[ky] = pack2(bb, bb);
            }
            #pragma unroll
            for (int i = 0; i < TY + 7; i++) {
                u64 v = *(const u64*)(p + i * TPITCH);
                #pragma unroll
                for (int ky = 0; ky < 8; ky++) {
                    int ty = i - ky;
                    if (ty >= 0 && ty < TY) {
                        accA[ty] = fma2(v, wA[ky], accA[ty]);
                        accB[ty] = fma2(v, wB[ky], accB[ty]);
                    }
                }
            }
        }
        // phase 2: ky 8..14, rows 8..29
        {
            u64 wA[7], wB[7];
            #pragma unroll
            for (int k2 = 0; k2 < 7; k2++) {
                int ky = k2 + 8;
                float a  = wsh[ky * KW + m];
                float bb = wsh[ky * KW + m + 1];
                wA[k2] = pack2(a, a);
                wB[k2] = pack2(bb, bb);
            }
            #pragma unroll
            for (int i = 8; i < TROWS; i++) {
                u64 v = *(const u64*)(p + i * TPITCH);
                #pragma unroll
                for (int k2 = 0; k2 < 7; k2++) {
                    int ty = i - (k2 + 8);
                    if (ty >= 0 && ty < TY) {
                        accA[ty] = fma2(v, wA[k2], accA[ty]);
                        accB[ty] = fma2(v, wB[k2], accB[ty]);
                    }
                }
            }
        }
    }
    // ---- tail kx = 14 (even, accA only) ----
    {
        const float* p = pc + (KW - 1);
        u64 wk[KH];
        #pragma unroll
        for (int ky = 0; ky < KH; ky++) {
            float a = wsh[ky * KW + (KW - 1)];
            wk[ky] = pack2(a, a);
        }
        #pragma unroll
        for (int i = 0; i < TROWS; i++) {
            u64 v = *(const u64*)(p + i * TPITCH);
            #pragma unroll
            for (int ky = 0; ky < KH; ky++) {
                int ty = i - ky;
                if (ty >= 0 && ty < TY)
                    accA[ty] = fma2(v, wk[ky], accA[ty]);
            }
        }
    }

    // ---- virtual staggered column for out(local 255): odd-kx partials ----
    // (warp-0 lanes 0..15, lane = ty; reads tile before overlay)
    float pext = 0.0f;
    if (tid < TY) {
        #pragma unroll
        for (int kx = 1; kx < KW; kx += 2) {
            #pragma unroll
            for (int ky = 0; ky < KH; ky++)
                pext = fmaf(tile[(tid + ky) * TPITCH + (BXO - 1) + kx],
                            wsh[ky * KW + kx], pext);
        }
    }
    __syncthreads();           // all tile reads done before overlay

    // ---- exchange accB.lo to neighbor t-1 via smem overlay ----
    float* exch = tile;        // overlay: [TY][XPITCH]
    #pragma unroll
    for (int ty = 0; ty < TY; ty++) {
        float lo, hi; unpack2(accB[ty], lo, hi);
        exch[ty * XPITCH + tid] = lo;
    }
    if (tid < TY) exch[tid * XPITCH + NT] = pext;
    __syncthreads();

    // ---- epilogue: combine + bias + packed store ----
    const int ox = gx0 + x0;
    if (ox < OW) {             // ox,OW even -> pair fits
        #pragma unroll
        for (int ty = 0; ty < TY; ty++) {
            int oy = gy0 + ty;
            if (oy < OH) {
                float alo, ahi; unpack2(accA[ty], alo, ahi);
                float blo, bhi; unpack2(accB[ty], blo, bhi);
                float o0 = alo + bhi + b;
                float o1 = ahi + exch[ty * XPITCH + tid + 1] + b;
                *(u64*)&out[(size_t)oy * OW + ox] = pack2(o0, o1);
            }
        }
    }
}

extern "C" void kernel_launch(void* const* d_in, const int* in_sizes, int n_in,
                              void* d_out, int out_size)
{
    const float* X    = (const float*)d_in[0];  // [4096,4096]
    const float* Wt   = (const float*)d_in[1];  // [15,15]
    const float* bias = (const float*)d_in[2];  // [1]
    float* out        = (float*)d_out;          // [4082,4082]

    dim3 grid((OW + BXO - 1) / BXO,   // 16
              (OH + TY - 1) / TY);    // 256
    conv15f_kernel<<<grid, NT>>>(X, Wt, bias, out);
}

// round 6
// speedup vs baseline: 1.3246x; 1.0472x over previous
#include <cuda_runtime.h>
#include <cuda_bf16.h>

// Conv2D 15x15 valid cross-correlation, 4096x4096 fp32 -> 4082x4082 fp32.
// Packed-fp32 (fma.rn.f32x2), parity-fused, register-lean (5 CTAs/SM).
//
// Each thread owns output x-pair (x0, x0+1), TY=14 rows.
// For kx-pair (m, m+1): ONE aligned LDS.64 at column x0+m feeds BOTH taps:
//   accA (lanes = out x0,   x0+1) += v * {w[ky][m],   w[ky][m]}
//   accB (lanes = out x0-1, x0  ) += v * {w[ky][m+1], w[ky][m+1]}
// ky is processed in 3 phases of 5 taps to cap live weight registers at 20.
// Epilogue: out(x0) = accA.lo + accB.hi (in-thread);
//           out(x0+1) = accA.hi + accB(t+1).lo via smem exchange;
//           block-edge staggered column computed by warp-0 lanes.

#define H_IN   4096
#define W_IN   4096
#define KH     15
#define KW     15
#define OH     (H_IN - KH + 1)   // 4082
#define OW     (W_IN - KW + 1)   // 4082

#define NT     128
#define BXO    (NT * 2)          // 256 output cols per block
#define TY     14                // output rows per thread
#define TROWS  (TY + KH - 1)     // 28
#define TCOLS  (BXO + KW - 1)    // 270
#define TPITCH 272               // even pitch, rows 16B-aligned
#define XPITCH 136               // exchange-overlay pitch (floats)

typedef unsigned long long u64;

__device__ __forceinline__ u64 pack2(float lo, float hi) {
    u64 r; asm("mov.b64 %0, {%1, %2};" : "=l"(r) : "f"(lo), "f"(hi)); return r;
}
__device__ __forceinline__ void unpack2(u64 v, float& lo, float& hi) {
    asm("mov.b64 {%0, %1}, %2;" : "=f"(lo), "=f"(hi) : "l"(v));
}
__device__ __forceinline__ u64 fma2(u64 a, u64 b, u64 c) {
    u64 d; asm("fma.rn.f32x2 %0, %1, %2, %3;" : "=l"(d) : "l"(a), "l"(b), "l"(c)); return d;
}

// One ky-phase [KY0, KY1] for kx-pair at columns (m, m+1), both parities.
template<int KY0, int KY1>
__device__ __forceinline__ void phaseAB(const float* __restrict__ p,
                                        const float* __restrict__ w,  // &wsh[m]
                                        u64 (&accA)[TY], u64 (&accB)[TY])
{
    const int NK = KY1 - KY0 + 1;
    u64 wA[NK], wB[NK];
    #pragma unroll
    for (int j = 0; j < NK; j++) {
        float a  = w[(KY0 + j) * KW];
        float bb = w[(KY0 + j) * KW + 1];
        wA[j] = pack2(a, a);
        wB[j] = pack2(bb, bb);
    }
    #pragma unroll
    for (int i = KY0; i <= TY - 1 + KY1; i++) {
        u64 v = *(const u64*)(p + i * TPITCH);
        #pragma unroll
        for (int j = 0; j < NK; j++) {
            int ty = i - (KY0 + j);
            if (ty >= 0 && ty < TY) {
                accA[ty] = fma2(v, wA[j], accA[ty]);
                accB[ty] = fma2(v, wB[j], accB[ty]);
            }
        }
    }
}

// One ky-phase, single parity (tail kx = 14).
template<int KY0, int KY1>
__device__ __forceinline__ void phaseA(const float* __restrict__ p,
                                       const float* __restrict__ w,   // &wsh[kx]
                                       u64 (&accA)[TY])
{
    const int NK = KY1 - KY0 + 1;
    u64 wA[NK];
    #pragma unroll
    for (int j = 0; j < NK; j++) {
        float a = w[(KY0 + j) * KW];
        wA[j] = pack2(a, a);
    }
    #pragma unroll
    for (int i = KY0; i <= TY - 1 + KY1; i++) {
        u64 v = *(const u64*)(p + i * TPITCH);
        #pragma unroll
        for (int j = 0; j < NK; j++) {
            int ty = i - (KY0 + j);
            if (ty >= 0 && ty < TY)
                accA[ty] = fma2(v, wA[j], accA[ty]);
        }
    }
}

__global__ __launch_bounds__(NT, 5)
void conv15g_kernel(const float* __restrict__ X,
                    const float* __restrict__ Wt,
                    const float* __restrict__ bias,
                    float* __restrict__ out)
{
    __shared__ __align__(16) float tile[TROWS * TPITCH];
    __shared__ float wsh[KH * KW];

    const int tid = threadIdx.x;
    const int gx0 = blockIdx.x * BXO;
    const int gy0 = blockIdx.y * TY;

    if (tid < KH * KW) wsh[tid] = Wt[tid];
    if (tid + NT < KH * KW) wsh[tid + NT] = Wt[tid + NT];

    // ---- tile fill (float4 fast path for interior blocks) ----
    if (gx0 + TPITCH <= W_IN && gy0 + TROWS <= H_IN) {
        const int NV = TPITCH / 4;  // 68 float4 per row
        #pragma unroll 4
        for (int i = tid; i < TROWS * NV; i += NT) {
            int r = i / NV;
            int c4 = i - r * NV;
            float4 v = *(const float4*)&X[(size_t)(gy0 + r) * W_IN + gx0 + 4 * c4];
            *(float4*)&tile[r * TPITCH + 4 * c4] = v;
        }
    } else {
        for (int i = tid; i < TROWS * TCOLS; i += NT) {
            int r = i / TCOLS;
            int c = i - r * TCOLS;
            int gy = gy0 + r; if (gy > H_IN - 1) gy = H_IN - 1;
            int gx = gx0 + c; if (gx > W_IN - 1) gx = W_IN - 1;
            tile[r * TPITCH + c] = X[(size_t)gy * W_IN + gx];
        }
    }
    const float b = bias[0];
    __syncthreads();

    const int x0 = 2 * tid;
    const float* pc = tile + x0;

    u64 accA[TY], accB[TY];
    #pragma unroll
    for (int t = 0; t < TY; t++) { accA[t] = 0ull; accB[t] = 0ull; }

    // ---- main loop: 7 kx-pairs x 3 ky-phases ----
    #pragma unroll 1
    for (int m = 0; m < KW - 1; m += 2) {
        const float* p = pc + m;
        const float* w = wsh + m;
        phaseAB<0, 4>  (p, w, accA, accB);
        phaseAB<5, 9>  (p, w, accA, accB);
        phaseAB<10, 14>(p, w, accA, accB);
    }
    // ---- tail kx = 14 (even, accA only) ----
    {
        const float* p = pc + (KW - 1);
        const float* w = wsh + (KW - 1);
        phaseA<0, 4>  (p, w, accA);
        phaseA<5, 9>  (p, w, accA);
        phaseA<10, 14>(p, w, accA);
    }

    // ---- virtual staggered column for out(local 255): odd-kx partials ----
    float pext = 0.0f;
    if (tid < TY) {
        #pragma unroll
        for (int kx = 1; kx < KW; kx += 2) {
            #pragma unroll
            for (int ky = 0; ky < KH; ky++)
                pext = fmaf(tile[(tid + ky) * TPITCH + (BXO - 1) + kx],
                            wsh[ky * KW + kx], pext);
        }
    }
    __syncthreads();           // all tile reads done before overlay

    // ---- exchange accB.lo to neighbor t-1 via smem overlay ----
    float* exch = tile;        // overlay: [TY][XPITCH]
    #pragma unroll
    for (int ty = 0; ty < TY; ty++) {
        float lo, hi; unpack2(accB[ty], lo, hi);
        exch[ty * XPITCH + tid] = lo;
    }
    if (tid < TY) exch[tid * XPITCH + NT] = pext;
    __syncthreads();

    // ---- epilogue: combine + bias + packed store ----
    const int ox = gx0 + x0;
    if (ox < OW) {             // ox,OW even -> pair fits
        #pragma unroll
        for (int ty = 0; ty < TY; ty++) {
            int oy = gy0 + ty;
            if (oy < OH) {
                float alo, ahi; unpack2(accA[ty], alo, ahi);
                float blo, bhi; unpack2(accB[ty], blo, bhi);
                float o0 = alo + bhi + b;
                float o1 = ahi + exch[ty * XPITCH + tid + 1] + b;
                *(u64*)&out[(size_t)oy * OW + ox] = pack2(o0, o1);
            }
        }
    }
}

extern "C" void kernel_launch(void* const* d_in, const int* in_sizes, int n_in,
                              void* d_out, int out_size)
{
    const float* X    = (const float*)d_in[0];  // [4096,4096]
    const float* Wt   = (const float*)d_in[1];  // [15,15]
    const float* bias = (const float*)d_in[2];  // [1]
    float* out        = (float*)d_out;          // [4082,4082]

    dim3 grid((OW + BXO - 1) / BXO,   // 16
              (OH + TY - 1) / TY);    // 292
    conv15g_kernel<<<grid, NT>>>(X, Wt, bias, out);
}